// round 12
// baseline (speedup 1.0000x reference)
#include <cuda_runtime.h>
#include <cuda_bf16.h>

// BuzzLoss: B=8192 rows, T=1024 cols.
// Per-warp autonomous cp.async double-buffered pipeline:
//   148 CTAs x 8 warps (1 CTA/SM, 128KB smem). Each warp loops over its rows
//   (row = globalWarp + k*1184): while computing row i from smem buffer b,
//   row i+1's 8KB (conf+acc) is in flight into buffer b^1 via cp.async.
//   Each lane stages and reads back ONLY its own 16 float4s -> completion is
//   the lane's own cp.async.wait_group; no warp/CTA sync in the loop.
// Compute per row = R8 math: segment reduction -> 8 interleaved warp
// product-scans -> 8-deep serial combine -> warp reduce.
// Single kernel: smem accumulate + ticket-based last-CTA finalize
// (self-resetting __device__ globals, graph-replay safe).

#define FULL_MASK 0xFFFFFFFFu
#define NUM_CTAS 148
#define THREADS 256
#define WARPS_PER_CTA 8
#define TOTAL_WARPS (NUM_CTAS * WARPS_PER_CTA)
// per warp: 2 buffers x 512 float4 (256 conf + 256 acc) = 16KB
#define SMEM_BYTES (WARPS_PER_CTA * 2 * 512 * 16)

__device__ float g_partial = 0.0f;
__device__ unsigned int g_ticket = 0u;

__device__ __forceinline__ void cp_async16(float4* smem_dst, const float4* gmem_src) {
    unsigned saddr = (unsigned)__cvta_generic_to_shared(smem_dst);
    asm volatile("cp.async.cg.shared.global [%0], [%1], 16;\n"
                 :: "r"(saddr), "l"(gmem_src));
}

__global__ __launch_bounds__(THREADS)
void buzz_loss_kernel(const float* __restrict__ conf,
                      const float* __restrict__ acc,
                      float* __restrict__ out,
                      int B, float negInvB) {
    extern __shared__ float4 smem[];

    const int tid  = threadIdx.x;
    const int lane = tid & 31;
    const int wid  = tid >> 5;
    const int gw   = blockIdx.x * WARPS_PER_CTA + wid;

    __shared__ float s_total;
    if (tid == 0) s_total = 0.0f;
    __syncthreads();

    float4* wbase = smem + wid * 1024;          // 2 buffers x 512

    // ---- stage row 'row' into buffer b (this lane's 16 float4s) ----
    auto issue_row = [&](int row, int b) {
        const float4* cg = reinterpret_cast<const float4*>(conf + (size_t)row * 1024);
        const float4* ag = reinterpret_cast<const float4*>(acc  + (size_t)row * 1024);
        float4* dst = wbase + b * 512;
        #pragma unroll
        for (int j = 0; j < 8; j++)
            cp_async16(&dst[j * 32 + lane], &cg[j * 32 + lane]);
        #pragma unroll
        for (int j = 0; j < 8; j++)
            cp_async16(&dst[256 + j * 32 + lane], &ag[j * 32 + lane]);
    };

    int row = gw;
    if (row < B) issue_row(row, 0);
    asm volatile("cp.async.commit_group;\n" ::: "memory");

    int buf = 0;
    float warpSum = 0.0f;

    while (row < B) {
        const int nrow = row + TOTAL_WARPS;
        if (nrow < B) issue_row(nrow, buf ^ 1);
        asm volatile("cp.async.commit_group;\n" ::: "memory");
        asm volatile("cp.async.wait_group 1;\n" ::: "memory");

        // ---- compute current row from buffer 'buf' ----
        const float4* rc = wbase + buf * 512;
        const float4* ra = rc + 256;

        float p[8], s1loc[8], s2loc[8];
        float lastA = 0.0f;

        #pragma unroll
        for (int j = 0; j < 8; j++) {
            const float4 c = rc[j * 32 + lane];
            const float4 a = ra[j * 32 + lane];

            const float q0 = 1.0f - c.x;
            const float q1 = 1.0f - c.y;
            const float q2 = 1.0f - c.z;
            const float q3 = 1.0f - c.w;

            const float lb0 = c.x;
            const float lb1 = c.y * q0;
            const float lb2 = c.z * (q0 * q1);
            const float lb3 = c.w * (q0 * q1 * q2);

            p[j] = (q0 * q1) * (q2 * q3);
            s1loc[j] = fmaf(lb0, a.x, fmaf(lb1, a.y, fmaf(lb2, a.z, lb3 * a.w)));
            s2loc[j] = (lb0 + lb1) + (lb2 + lb3);

            if (j == 7) lastA = a.w;        // lane 31 -> acc[row, 1023]
        }

        #pragma unroll
        for (int d = 1; d < 32; d <<= 1) {
            #pragma unroll
            for (int j = 0; j < 8; j++) {
                float v = __shfl_up_sync(FULL_MASK, p[j], d);
                if (lane >= d) p[j] *= v;
            }
        }

        float R = 1.0f, s1 = 0.0f, s2 = 0.0f;
        #pragma unroll
        for (int j = 0; j < 8; j++) {
            const float tot = __shfl_sync(FULL_MASK, p[j], 31);
            float E = __shfl_up_sync(FULL_MASK, p[j], 1);
            if (lane == 0) E = 1.0f;
            const float Ej = E * R;
            s1 = fmaf(Ej, s1loc[j], s1);
            s2 = fmaf(Ej, s2loc[j], s2);
            R *= tot;
        }

        #pragma unroll
        for (int d = 16; d >= 1; d >>= 1) {
            s1 += __shfl_down_sync(FULL_MASK, s1, d);
            s2 += __shfl_down_sync(FULL_MASK, s2, d);
        }
        const float accLast = __shfl_sync(FULL_MASK, lastA, 31);

        if (lane == 0) {
            warpSum += s1 + (1.0f - s2) * accLast;
        }

        row = nrow;
        buf ^= 1;
    }

    if (lane == 0 && warpSum != 0.0f) {
        atomicAdd(&s_total, warpSum);
    } else if (lane == 0) {
        atomicAdd(&s_total, warpSum);   // keep deterministic simple path
    }
    __syncthreads();

    // ---- ticket-based last-CTA finalize (self-resetting) ----
    if (tid == 0) {
        atomicAdd(&g_partial, s_total);
        __threadfence();
        const unsigned t = atomicAdd(&g_ticket, 1u);
        if (t == gridDim.x - 1) {
            const float total = atomicExch(&g_partial, 0.0f);
            atomicExch(&g_ticket, 0u);
            out[0] = total * negInvB;
        }
    }
}

extern "C" void kernel_launch(void* const* d_in, const int* in_sizes, int n_in,
                              void* d_out, int out_size) {
    const float* conf = (const float*)d_in[0];
    const float* acc  = (const float*)d_in[1];
    float* out = (float*)d_out;

    const int total = in_sizes[0];
    const int T = 1024;
    const int B = total / T;

    cudaFuncSetAttribute(buzz_loss_kernel,
                         cudaFuncAttributeMaxDynamicSharedMemorySize,
                         SMEM_BYTES);

    buzz_loss_kernel<<<NUM_CTAS, THREADS, SMEM_BYTES>>>(conf, acc, out,
                                                        B, -1.0f / (float)B);
}

// round 13
// speedup vs baseline: 1.4915x; 1.4915x over previous
#include <cuda_runtime.h>
#include <cuda_bf16.h>

// BuzzLoss: B=8192 rows, T=1024 cols.
// Best-known structure (R7/R8): ONE WARP PER ROW, 8 rows per 256-thread CTA,
// lane l owns elements {j*128 + 4l + e}; 16 coalesced LDG.128 per warp with
// per-segment reduction on arrival to (p, s1loc, s2loc); 8 interleaved warp
// product-scans; 8-deep serial combine.
// Changes vs R8 (overhead removal only):
//  - single kernel: ticket-based last-CTA finalize with self-resetting
//    __device__ globals (removes the zero-kernel graph node)
//  - accLast folded BEFORE the warp reduce: one reduced value (5 shfls, not 10)

#define FULL_MASK 0xFFFFFFFFu
#define ROWS_PER_CTA 8

__device__ float g_partial = 0.0f;
__device__ unsigned int g_ticket = 0u;

__global__ __launch_bounds__(256)
void buzz_loss_kernel(const float* __restrict__ conf,
                      const float* __restrict__ acc,
                      float* __restrict__ out,
                      float negInvB) {
    const int tid  = threadIdx.x;
    const int lane = tid & 31;
    const int wid  = tid >> 5;
    const size_t row = (size_t)blockIdx.x * ROWS_PER_CTA + wid;

    __shared__ float s_total;
    if (tid == 0) s_total = 0.0f;
    __syncthreads();

    const float4* c4 = reinterpret_cast<const float4*>(conf + row * 1024) + lane;
    const float4* a4 = reinterpret_cast<const float4*>(acc  + row * 1024) + lane;

    // ---- Phase 1: load + immediate per-segment reduction ----
    float p[8], s1loc[8], s2loc[8];
    float lastA = 0.0f;

    #pragma unroll
    for (int j = 0; j < 8; j++) {
        const float4 c = c4[j * 32];
        const float4 a = a4[j * 32];

        const float q0 = 1.0f - c.x;
        const float q1 = 1.0f - c.y;
        const float q2 = 1.0f - c.z;
        const float q3 = 1.0f - c.w;

        const float lb0 = c.x;
        const float lb1 = c.y * q0;
        const float lb2 = c.z * (q0 * q1);
        const float lb3 = c.w * (q0 * q1 * q2);

        p[j] = (q0 * q1) * (q2 * q3);
        s1loc[j] = fmaf(lb0, a.x, fmaf(lb1, a.y, fmaf(lb2, a.z, lb3 * a.w)));
        s2loc[j] = (lb0 + lb1) + (lb2 + lb3);

        if (j == 7) lastA = a.w;           // lane 31 -> acc[row, 1023]
    }

    // ---- Phase 2: 8 interleaved warp inclusive product-scans ----
    #pragma unroll
    for (int d = 1; d < 32; d <<= 1) {
        #pragma unroll
        for (int j = 0; j < 8; j++) {
            float v = __shfl_up_sync(FULL_MASK, p[j], d);
            if (lane >= d) p[j] *= v;
        }
    }

    float tot[8], E[8];
    #pragma unroll
    for (int j = 0; j < 8; j++) {
        tot[j] = __shfl_sync(FULL_MASK, p[j], 31);
        E[j]   = __shfl_up_sync(FULL_MASK, p[j], 1);
        if (lane == 0) E[j] = 1.0f;
    }

    // Serial cross-segment chain (8 deep)
    float R = 1.0f, s1 = 0.0f, s2 = 0.0f;
    #pragma unroll
    for (int j = 0; j < 8; j++) {
        const float Ej = E[j] * R;
        s1 = fmaf(Ej, s1loc[j], s1);
        s2 = fmaf(Ej, s2loc[j], s2);
        R *= tot[j];
    }

    // Fold accLast BEFORE the reduce: score_contrib = s1 - accLast*s2, and
    // lane 31 adds the constant accLast term once.
    const float accLast = __shfl_sync(FULL_MASK, lastA, 31);
    float contrib = fmaf(-accLast, s2, s1);
    if (lane == 31) contrib += accLast;

    // Single-value warp reduce (5 shfls)
    #pragma unroll
    for (int d = 16; d >= 1; d >>= 1) {
        contrib += __shfl_down_sync(FULL_MASK, contrib, d);
    }

    if (lane == 0) {
        atomicAdd(&s_total, contrib);
    }
    __syncthreads();

    // ---- ticket-based last-CTA finalize (self-resetting, replay-safe) ----
    if (tid == 0) {
        atomicAdd(&g_partial, s_total);
        __threadfence();
        const unsigned t = atomicAdd(&g_ticket, 1u);
        if (t == gridDim.x - 1) {
            const float total = atomicExch(&g_partial, 0.0f);
            atomicExch(&g_ticket, 0u);
            out[0] = total * negInvB;
        }
    }
}

extern "C" void kernel_launch(void* const* d_in, const int* in_sizes, int n_in,
                              void* d_out, int out_size) {
    const float* conf = (const float*)d_in[0];
    const float* acc  = (const float*)d_in[1];
    float* out = (float*)d_out;

    const int total = in_sizes[0];
    const int T = 1024;
    const int B = total / T;

    buzz_loss_kernel<<<B / ROWS_PER_CTA, 256>>>(conf, acc, out,
                                                -1.0f / (float)B);
}